// round 12
// baseline (speedup 1.0000x reference)
#include <cuda_runtime.h>
#include <cstdint>

#define Bdim 256
#define Udim 512
#define Ddim 512
#define N4U  2048

typedef unsigned long long ull;

// ---------------- scratch ----------------
__device__ float g_pre  [Bdim * N4U];
__device__ float g_hw   [Bdim * Udim];
__device__ float g_red16[Bdim * 16 * Udim];
__device__ float g_g    [Bdim * Udim];
__device__ int   d_gemm_cnt;
__device__ int   d_red_cnt[Bdim];
__device__ int   d_flag[Bdim];

// ---------------- packed f32x2 helpers ----------------
__device__ __forceinline__ ull pk2(float x, float y) {
    ull r; asm("mov.b64 %0, {%1, %2};" : "=l"(r) : "f"(x), "f"(y)); return r;
}
__device__ __forceinline__ ull fma2(ull a, ull b, ull c) {
    ull d; asm("fma.rn.f32x2 %0, %1, %2, %3;" : "=l"(d) : "l"(a), "l"(b), "l"(c)); return d;
}
__device__ __forceinline__ float2 upk(ull v) {
    float2 r; asm("mov.b64 {%0, %1}, %2;" : "=f"(r.x), "=f"(r.y) : "l"(v)); return r;
}
__device__ __forceinline__ float hsig(float z) {
    return fminf(fmaxf(0.2f * z + 0.5f, 0.f), 1.f);
}

// ---------------- init: reset sync state each replay ----------------
__global__ void init_kernel() {
    int i = threadIdx.x;
    if (i == 0) d_gemm_cnt = 0;
    if (i < Bdim) { d_red_cnt[i] = 0; d_flag[i] = 0; }
}

// ---------------- GEMM tile ----------------
__device__ __forceinline__ void gemm32x64(
    const float* __restrict__ A1, const float* __restrict__ B1,
    const float* __restrict__ A2, const float* __restrict__ B2,
    const float* __restrict__ bias, float* __restrict__ C,
    int N, int m0, int n0, bool do_rec, bool add_bias, float* smem)
{
    const int K = 512;
    float (*As)[32] = (float(*)[32])smem;
    float (*Bs)[64] = (float(*)[64])(smem + 512);

    int tid = threadIdx.x;
    int tx  = tid & 15;
    int ty  = tid >> 4;

    ull acc[2][2];
    acc[0][0] = acc[0][1] = acc[1][0] = acc[1][1] = 0ull;

    int npass = do_rec ? 2 : 1;
    for (int pass = 0; pass < npass; ++pass) {
        const float* A = pass ? A2 : A1;
        const float* B = pass ? B2 : B1;
        for (int k0 = 0; k0 < K; k0 += 16) {
            #pragma unroll
            for (int t = 0; t < 2; ++t) {
                int i = tid + t * 256;
                As[i & 15][i >> 4] = A[(m0 + (i >> 4)) * K + k0 + (i & 15)];
            }
            #pragma unroll
            for (int t = 0; t < 4; ++t) {
                int i = tid + t * 256;
                Bs[i >> 6][i & 63] = B[(k0 + (i >> 6)) * N + n0 + (i & 63)];
            }
            __syncthreads();
            #pragma unroll
            for (int kk = 0; kk < 16; ++kk) {
                float2 av = *(const float2*)&As[kk][ty * 2];
                ulonglong2 bv = *(const ulonglong2*)&Bs[kk][tx * 4];
                ull a0 = pk2(av.x, av.x);
                ull a1 = pk2(av.y, av.y);
                acc[0][0] = fma2(a0, bv.x, acc[0][0]);
                acc[0][1] = fma2(a0, bv.y, acc[0][1]);
                acc[1][0] = fma2(a1, bv.x, acc[1][0]);
                acc[1][1] = fma2(a1, bv.y, acc[1][1]);
            }
            __syncthreads();
        }
    }

    int n = n0 + tx * 4;
    float b0 = 0.f, b1 = 0.f, b2 = 0.f, b3 = 0.f;
    if (add_bias) { b0 = bias[n]; b1 = bias[n+1]; b2 = bias[n+2]; b3 = bias[n+3]; }
    #pragma unroll
    for (int r = 0; r < 2; ++r) {
        int m = m0 + ty * 2 + r;
        float2 lo = upk(acc[r][0]);
        float2 hi = upk(acc[r][1]);
        float4 o = make_float4(lo.x + b0, lo.y + b1, hi.x + b2, hi.y + b3);
        *(float4*)&C[m * N + n] = o;
    }
}

// =======================================================================
// Mega kernel: GEMM | reduce | {combine, update} producer-consumer
//   [0,320)        GEMMs
//   [320,4416)     reduce: t=bid-320, b=t>>4, chunk=t&15
//   [4416,21056)   per b (65 blocks): r==0 combine, r-1 in [0,64) update
// =======================================================================
__global__ void __launch_bounds__(256) mega_kernel(
    const float* __restrict__ x,     const float* __restrict__ kernel,
    const float* __restrict__ h_tm1, const float* __restrict__ rec,
    const float* __restrict__ bias,  const float* __restrict__ w,
    const float* __restrict__ hebb,  const float* __restrict__ c_tm1,
    const float* __restrict__ alpha, const float* __restrict__ h2mod,
    const float* __restrict__ fanout, float* __restrict__ out)
{
    __shared__ __align__(16) float smem[1536];
    int bid = blockIdx.x;
    int tid = threadIdx.x;

    if (bid < 320) {
        // ---------------- GEMMs ----------------
        if (bid < 256) {
            int n0 = (bid & 31) * 64;
            int m0 = (bid >> 5) * 32;
            bool do_rec = !(n0 >= 2 * Udim && n0 < 3 * Udim);  // c-slice: no rec
            gemm32x64(x, kernel, h_tm1, rec, bias, g_pre, N4U, m0, n0, do_rec, true, smem);
        } else {
            int t  = bid - 256;
            int n0 = (t & 7) * 64;
            int m0 = (t >> 3) * 32;
            gemm32x64(h_tm1, w, nullptr, nullptr, nullptr, g_hw, Udim, m0, n0, false, false, smem);
        }
        __syncthreads();
        if (tid == 0) { __threadfence(); atomicAdd(&d_gemm_cnt, 1); }
        return;
    }

    if (bid < 4416) {
        // ---------------- hebb partial reduce (plain loads -> L2) ----------------
        int t     = bid - 320;
        int b     = t >> 4;
        int chunk = t & 15;
        int v4    = tid & 127;
        int uh    = tid >> 7;

        ull* hs2 = (ull*)smem;
        if (tid < 32) {
            float hv = h_tm1[(b << 9) + (chunk << 5) + tid];
            hs2[tid] = pk2(hv, hv);
        }
        __syncthreads();

        const float4* p = (const float4*)(hebb
            + ((size_t)b << 18)
            + ((size_t)(chunk * 32 + uh * 16) << 9)) + v4;
        const ull* hb = hs2 + uh * 16;

        ull a0x = 0, a0y = 0, a1x = 0, a1y = 0;
        ull a2x = 0, a2y = 0, a3x = 0, a3y = 0;
        #pragma unroll
        for (int k = 0; k < 4; ++k) {
            float4 l0 = p[(size_t)(k * 4 + 0) * 128];
            float4 l1 = p[(size_t)(k * 4 + 1) * 128];
            float4 l2 = p[(size_t)(k * 4 + 2) * 128];
            float4 l3 = p[(size_t)(k * 4 + 3) * 128];
            ull h0 = hb[k * 4 + 0], h1 = hb[k * 4 + 1];
            ull h2 = hb[k * 4 + 2], h3 = hb[k * 4 + 3];
            ulonglong2 v0 = *(ulonglong2*)&l0;
            ulonglong2 v1 = *(ulonglong2*)&l1;
            ulonglong2 v2 = *(ulonglong2*)&l2;
            ulonglong2 v3 = *(ulonglong2*)&l3;
            a0x = fma2(h0, v0.x, a0x);  a0y = fma2(h0, v0.y, a0y);
            a1x = fma2(h1, v1.x, a1x);  a1y = fma2(h1, v1.y, a1y);
            a2x = fma2(h2, v2.x, a2x);  a2y = fma2(h2, v2.y, a2y);
            a3x = fma2(h3, v3.x, a3x);  a3y = fma2(h3, v3.y, a3y);
        }
        float2 s0 = upk(a0x), s1 = upk(a1x), s2 = upk(a2x), s3 = upk(a3x);
        float2 t0 = upk(a0y), t1 = upk(a1y), t2 = upk(a2y), t3 = upk(a3y);
        float4 acc = make_float4((s0.x + s1.x) + (s2.x + s3.x),
                                 (s0.y + s1.y) + (s2.y + s3.y),
                                 (t0.x + t1.x) + (t2.x + t3.x),
                                 (t0.y + t1.y) + (t2.y + t3.y));

        __syncthreads();
        float4* st = (float4*)(smem + 256);
        if (uh == 1) st[v4] = acc;
        __syncthreads();
        if (uh == 0) {
            float4 o = st[v4];
            acc.x += o.x; acc.y += o.y; acc.z += o.z; acc.w += o.w;
            ((float4*)(g_red16 + (size_t)(b * 16 + chunk) * Udim))[v4] = acc;
        }
        __syncthreads();
        if (tid == 0) { __threadfence(); atomicAdd(&d_red_cnt[b], 1); }
        return;
    }

    int t2 = bid - 4416;
    int b  = t2 / 65;
    int r  = t2 % 65;

    if (r == 0) {
        // ---------------- combine(b): 256 threads, 2 v each ----------------
        if (tid == 0) {
            while (*(volatile int*)&d_gemm_cnt < 320) __nanosleep(64);
            while (*(volatile int*)&d_red_cnt[b] < 16) __nanosleep(64);
        }
        __syncthreads();
        __threadfence();

        float hva[2], itca[2];
        #pragma unroll
        for (int half = 0; half < 2; ++half) {
            int v = tid + half * 256;
            const float* rr = g_red16 + (size_t)b * 16 * Udim + v;
            float p0 = 0.f, p1 = 0.f, p2 = 0.f, p3 = 0.f;
            #pragma unroll
            for (int j = 0; j < 16; j += 4) {
                p0 += rr[(j + 0) * Udim];
                p1 += rr[(j + 1) * Udim];
                p2 += rr[(j + 2) * Udim];
                p3 += rr[(j + 3) * Udim];
            }
            float red = (p0 + p1) + (p2 + p3);

            float xi = g_pre[b * N4U + v];
            float xf = g_pre[b * N4U + Udim + v];
            float xc = g_pre[b * N4U + 2 * Udim + v];
            float xo = g_pre[b * N4U + 3 * Udim + v];

            float gi = hsig(xi), gf = hsig(xf), go = hsig(xo);
            float itc = tanhf(xc + g_hw[b * Udim + v] + alpha[v] * red);
            float c = gf * c_tm1[b * Udim + v] + gi * itc;
            float h = go * tanhf(c);

            out[b * Udim + v] = h;
            out[Bdim * Udim + b * Udim + v] = c;
            hva[half] = h * h2mod[v];
            itca[half] = itc;
        }

        float s = hva[0] + hva[1];
        #pragma unroll
        for (int o = 16; o > 0; o >>= 1) s += __shfl_down_sync(0xffffffffu, s, o);
        float* ws = smem;          // 8 warps
        if ((tid & 31) == 0) ws[tid >> 5] = s;
        __syncthreads();
        if (tid == 0) {
            float tot = ((ws[0] + ws[1]) + (ws[2] + ws[3]))
                      + ((ws[4] + ws[5]) + (ws[6] + ws[7]));
            smem[8] = tanhf(tot);
        }
        __syncthreads();
        float eta = smem[8];

        g_g[b * Udim + tid]       = eta * fanout[tid]       * itca[0];
        g_g[b * Udim + tid + 256] = eta * fanout[tid + 256] * itca[1];

        __syncthreads();
        if (tid == 0) {
            __threadfence();
            *(volatile int*)&d_flag[b] = 1;
        }
        return;
    }

    // ---------------- update(b): 64 blocks x 1024 f4 ----------------
    {
        int j = r - 1;
        if (tid == 0) {
            while (*(volatile int*)&d_flag[b] == 0) __nanosleep(64);
        }
        __syncthreads();
        __threadfence();

        float* outh = out + 2 * Bdim * Udim;
        int lbase = j * 1024 + tid;            // local f4 within b
        #pragma unroll
        for (int k = 0; k < 4; ++k) {
            int l   = lbase + k * 256;
            int u   = l >> 7;
            int v4  = l & 127;
            int idx = (b << 16) + l;

            float hu = h_tm1[(b << 9) + u];
            float4 hv = ((const float4*)hebb)[idx];            // L2-hot hopefully
            float4 gg = ((const float4*)(g_g + b * Udim))[v4];

            float4 rr;
            rr.x = fminf(fmaxf(hv.x + hu * gg.x, -2.f), 2.f);
            rr.y = fminf(fmaxf(hv.y + hu * gg.y, -2.f), 2.f);
            rr.z = fminf(fmaxf(hv.z + hu * gg.z, -2.f), 2.f);
            rr.w = fminf(fmaxf(hv.w + hu * gg.w, -2.f), 2.f);
            __stcs(((float4*)outh) + idx, rr);
        }
    }
}

// ---------------- launch ----------------
extern "C" void kernel_launch(void* const* d_in, const int* in_sizes, int n_in,
                              void* d_out, int out_size)
{
    const float* x      = (const float*)d_in[0];
    const float* h_tm1  = (const float*)d_in[1];
    const float* c_tm1  = (const float*)d_in[2];
    const float* hebb   = (const float*)d_in[3];
    const float* kernel = (const float*)d_in[4];
    const float* rec    = (const float*)d_in[5];
    const float* bias   = (const float*)d_in[6];
    const float* w      = (const float*)d_in[7];
    const float* alpha  = (const float*)d_in[8];
    const float* h2mod  = (const float*)d_in[9];
    const float* fanout = (const float*)d_in[10];
    float* out = (float*)d_out;

    init_kernel<<<1, 512>>>();
    mega_kernel<<<4416 + 256 * 65, 256>>>(x, kernel, h_tm1, rec, bias, w,
                                          hebb, c_tm1, alpha, h2mod, fanout, out);
}

// round 13
// speedup vs baseline: 1.2375x; 1.2375x over previous
#include <cuda_runtime.h>
#include <cstdint>

#define Bdim 256
#define Udim 512
#define Ddim 512
#define N4U  2048

typedef unsigned long long ull;

// ---------------- scratch ----------------
__device__ float g_pre  [Bdim * N4U];
__device__ float g_hw   [Bdim * Udim];
__device__ float g_red16[Bdim * 16 * Udim];
__device__ float g_g    [Bdim * Udim];
__device__ int   d_gemm_cnt;
__device__ int   d_red_cnt[Bdim];
__device__ int   d_flag[Bdim];

// ---------------- packed f32x2 helpers ----------------
__device__ __forceinline__ ull pk2(float x, float y) {
    ull r; asm("mov.b64 %0, {%1, %2};" : "=l"(r) : "f"(x), "f"(y)); return r;
}
__device__ __forceinline__ ull fma2(ull a, ull b, ull c) {
    ull d; asm("fma.rn.f32x2 %0, %1, %2, %3;" : "=l"(d) : "l"(a), "l"(b), "l"(c)); return d;
}
__device__ __forceinline__ float2 upk(ull v) {
    float2 r; asm("mov.b64 {%0, %1}, %2;" : "=f"(r.x), "=f"(r.y) : "l"(v)); return r;
}
__device__ __forceinline__ float hsig(float z) {
    return fminf(fmaxf(0.2f * z + 0.5f, 0.f), 1.f);
}

// ---------------- init: reset sync state each replay ----------------
__global__ void init_kernel() {
    int i = threadIdx.x;
    if (i == 0) d_gemm_cnt = 0;
    if (i < Bdim) { d_red_cnt[i] = 0; d_flag[i] = 0; }
}

// ---------------- GEMM tile (uses dynamic smem base) ----------------
__device__ __forceinline__ void gemm32x64(
    const float* __restrict__ A1, const float* __restrict__ B1,
    const float* __restrict__ A2, const float* __restrict__ B2,
    const float* __restrict__ bias, float* __restrict__ C,
    int N, int m0, int n0, bool do_rec, bool add_bias, float* smem)
{
    const int K = 512;
    float (*As)[32] = (float(*)[32])smem;
    float (*Bs)[64] = (float(*)[64])(smem + 512);

    int tid = threadIdx.x;
    int tx  = tid & 15;
    int ty  = tid >> 4;

    ull acc[2][2];
    acc[0][0] = acc[0][1] = acc[1][0] = acc[1][1] = 0ull;

    int npass = do_rec ? 2 : 1;
    for (int pass = 0; pass < npass; ++pass) {
        const float* A = pass ? A2 : A1;
        const float* B = pass ? B2 : B1;
        for (int k0 = 0; k0 < K; k0 += 16) {
            #pragma unroll
            for (int t = 0; t < 2; ++t) {
                int i = tid + t * 256;
                As[i & 15][i >> 4] = A[(m0 + (i >> 4)) * K + k0 + (i & 15)];
            }
            #pragma unroll
            for (int t = 0; t < 4; ++t) {
                int i = tid + t * 256;
                Bs[i >> 6][i & 63] = B[(k0 + (i >> 6)) * N + n0 + (i & 63)];
            }
            __syncthreads();
            #pragma unroll
            for (int kk = 0; kk < 16; ++kk) {
                float2 av = *(const float2*)&As[kk][ty * 2];
                ulonglong2 bv = *(const ulonglong2*)&Bs[kk][tx * 4];
                ull a0 = pk2(av.x, av.x);
                ull a1 = pk2(av.y, av.y);
                acc[0][0] = fma2(a0, bv.x, acc[0][0]);
                acc[0][1] = fma2(a0, bv.y, acc[0][1]);
                acc[1][0] = fma2(a1, bv.x, acc[1][0]);
                acc[1][1] = fma2(a1, bv.y, acc[1][1]);
            }
            __syncthreads();
        }
    }

    int n = n0 + tx * 4;
    float b0 = 0.f, b1 = 0.f, b2 = 0.f, b3 = 0.f;
    if (add_bias) { b0 = bias[n]; b1 = bias[n+1]; b2 = bias[n+2]; b3 = bias[n+3]; }
    #pragma unroll
    for (int r = 0; r < 2; ++r) {
        int m = m0 + ty * 2 + r;
        float2 lo = upk(acc[r][0]);
        float2 hi = upk(acc[r][1]);
        float4 o = make_float4(lo.x + b0, lo.y + b1, hi.x + b2, hi.y + b3);
        *(float4*)&C[m * N + n] = o;
    }
}

// =======================================================================
// Mega kernel, read-hebb-ONCE design:
//   [0,320)      GEMM blocks (retire in wave 1)
//   [320,4416)   per (b, 32-u chunk): load chunk -> SMEM while reducing,
//                publish partial, (chunk==15: combine), wait flag,
//                update from SMEM copy, stream out. 68KB dyn smem.
// =======================================================================
__global__ void __launch_bounds__(256) mega_kernel(
    const float* __restrict__ x,     const float* __restrict__ kernel,
    const float* __restrict__ h_tm1, const float* __restrict__ rec,
    const float* __restrict__ bias,  const float* __restrict__ w,
    const float* __restrict__ hebb,  const float* __restrict__ c_tm1,
    const float* __restrict__ alpha, const float* __restrict__ h2mod,
    const float* __restrict__ fanout, float* __restrict__ out)
{
    extern __shared__ __align__(16) float dsm[];
    // layout (floats): data[16384] | fold[512] | hs2(ull)[32]=64 | ws[16] | eta[1]
    float* data = dsm;
    float* fold = dsm + 16384;
    ull*   hs2  = (ull*)(dsm + 16896);
    float* ws   = dsm + 16960;

    int bid = blockIdx.x;
    int tid = threadIdx.x;

    if (bid < 320) {
        if (bid < 256) {
            int n0 = (bid & 31) * 64;
            int m0 = (bid >> 5) * 32;
            bool do_rec = !(n0 >= 2 * Udim && n0 < 3 * Udim);  // c-slice: no rec
            gemm32x64(x, kernel, h_tm1, rec, bias, g_pre, N4U, m0, n0, do_rec, true, dsm);
        } else {
            int t  = bid - 256;
            int n0 = (t & 7) * 64;
            int m0 = (t >> 3) * 32;
            gemm32x64(h_tm1, w, nullptr, nullptr, nullptr, g_hw, Udim, m0, n0, false, false, dsm);
        }
        __syncthreads();
        if (tid == 0) { __threadfence(); atomicAdd(&d_gemm_cnt, 1); }
        return;
    }

    // ---------------- reduce + keep chunk in SMEM ----------------
    int t     = bid - 320;        // 0..4095
    int b     = t >> 4;
    int chunk = t & 15;           // 32-u chunk
    int v4    = tid & 127;
    int uh    = tid >> 7;         // 16-u half

    if (tid < 32) {
        float hv = h_tm1[(b << 9) + (chunk << 5) + tid];
        hs2[tid] = pk2(hv, hv);
    }
    __syncthreads();

    const float4* src = (const float4*)(hebb
        + ((size_t)b << 18)
        + ((size_t)(chunk * 32 + uh * 16) << 9)) + v4;
    float4* drow = (float4*)data + (uh * 16) * 128 + v4;
    const ull* hb = hs2 + uh * 16;

    ull ax = 0ull, ay = 0ull;
    #pragma unroll
    for (int k = 0; k < 16; ++k) {
        float4 l = __ldcs(src + (size_t)k * 128);
        drow[k * 128] = l;                      // stash for the update pass
        ulonglong2 lv = *(ulonglong2*)&l;
        ull hd = hb[k];
        ax = fma2(hd, lv.x, ax);
        ay = fma2(hd, lv.y, ay);
    }
    float2 fx = upk(ax), fy = upk(ay);
    float4 acc = make_float4(fx.x, fx.y, fy.x, fy.y);

    __syncthreads();
    if (uh == 1) ((float4*)fold)[v4] = acc;
    __syncthreads();
    if (uh == 0) {
        float4 o = ((float4*)fold)[v4];
        acc.x += o.x; acc.y += o.y; acc.z += o.z; acc.w += o.w;
        ((float4*)(g_red16 + (size_t)(b * 16 + chunk) * Udim))[v4] = acc;
    }
    __syncthreads();
    if (tid == 0) { __threadfence(); atomicAdd(&d_red_cnt[b], 1); }

    // ---------------- combine(b), done by the chunk==15 block ----------------
    if (chunk == 15) {
        if (tid == 0) {
            while (*(volatile int*)&d_gemm_cnt < 320) __nanosleep(32);
            while (*(volatile int*)&d_red_cnt[b] < 16) __nanosleep(32);
        }
        __syncthreads();
        __threadfence();

        float hva[2], itca[2];
        #pragma unroll
        for (int half = 0; half < 2; ++half) {
            int v = tid + half * 256;
            const float* rr = g_red16 + (size_t)b * 16 * Udim + v;
            float p0 = 0.f, p1 = 0.f, p2 = 0.f, p3 = 0.f;
            #pragma unroll
            for (int j = 0; j < 16; j += 4) {
                p0 += rr[(j + 0) * Udim];
                p1 += rr[(j + 1) * Udim];
                p2 += rr[(j + 2) * Udim];
                p3 += rr[(j + 3) * Udim];
            }
            float red = (p0 + p1) + (p2 + p3);

            float xi = g_pre[b * N4U + v];
            float xf = g_pre[b * N4U + Udim + v];
            float xc = g_pre[b * N4U + 2 * Udim + v];
            float xo = g_pre[b * N4U + 3 * Udim + v];

            float gi = hsig(xi), gf = hsig(xf), go = hsig(xo);
            float itc = tanhf(xc + g_hw[b * Udim + v] + alpha[v] * red);
            float c = gf * c_tm1[b * Udim + v] + gi * itc;
            float h = go * tanhf(c);

            out[b * Udim + v] = h;
            out[Bdim * Udim + b * Udim + v] = c;
            hva[half] = h * h2mod[v];
            itca[half] = itc;
        }

        float s = hva[0] + hva[1];
        #pragma unroll
        for (int o = 16; o > 0; o >>= 1) s += __shfl_down_sync(0xffffffffu, s, o);
        if ((tid & 31) == 0) ws[tid >> 5] = s;
        __syncthreads();
        if (tid == 0) {
            float tot = ((ws[0] + ws[1]) + (ws[2] + ws[3]))
                      + ((ws[4] + ws[5]) + (ws[6] + ws[7]));
            ws[8] = tanhf(tot);
        }
        __syncthreads();
        float eta = ws[8];

        g_g[b * Udim + tid]       = eta * fanout[tid]       * itca[0];
        g_g[b * Udim + tid + 256] = eta * fanout[tid + 256] * itca[1];

        __syncthreads();
        if (tid == 0) {
            __threadfence();
            *(volatile int*)&d_flag[b] = 1;
        }
        __syncthreads();   // own writes ordered for own read below
    } else {
        if (tid == 0) {
            while (*(volatile int*)&d_flag[b] == 0) __nanosleep(32);
        }
        __syncthreads();
        __threadfence();
    }

    // ---------------- update from the SMEM copy ----------------
    float4 gv = ((const float4*)(g_g + (b << 9)))[v4];
    float* outh = out + 2 * Bdim * Udim;
    float4* dst = (float4*)outh + (b << 16) + ((chunk * 32 + uh * 16) << 7) + v4;

    #pragma unroll
    for (int k = 0; k < 16; ++k) {
        float4 hv = drow[k * 128];
        float hu = upk(hb[k]).x;
        float4 r;
        r.x = fminf(fmaxf(hv.x + hu * gv.x, -2.f), 2.f);
        r.y = fminf(fmaxf(hv.y + hu * gv.y, -2.f), 2.f);
        r.z = fminf(fmaxf(hv.z + hu * gv.z, -2.f), 2.f);
        r.w = fminf(fmaxf(hv.w + hu * gv.w, -2.f), 2.f);
        __stcs(dst + k * 128, r);
    }
}

// ---------------- launch ----------------
extern "C" void kernel_launch(void* const* d_in, const int* in_sizes, int n_in,
                              void* d_out, int out_size)
{
    const float* x      = (const float*)d_in[0];
    const float* h_tm1  = (const float*)d_in[1];
    const float* c_tm1  = (const float*)d_in[2];
    const float* hebb   = (const float*)d_in[3];
    const float* kernel = (const float*)d_in[4];
    const float* rec    = (const float*)d_in[5];
    const float* bias   = (const float*)d_in[6];
    const float* w      = (const float*)d_in[7];
    const float* alpha  = (const float*)d_in[8];
    const float* h2mod  = (const float*)d_in[9];
    const float* fanout = (const float*)d_in[10];
    float* out = (float*)d_out;

    const int DSMEM = 69632;   // 68KB
    static bool attr_set = false;
    if (!attr_set) {
        cudaFuncSetAttribute(mega_kernel,
                             cudaFuncAttributeMaxDynamicSharedMemorySize, DSMEM);
        attr_set = true;
    }

    init_kernel<<<1, 512>>>();
    mega_kernel<<<320 + 4096, 256, DSMEM>>>(x, kernel, h_tm1, rec, bias, w,
                                            hebb, c_tm1, alpha, h2mod, fanout, out);
}